// round 16
// baseline (speedup 1.0000x reference)
#include <cuda_runtime.h>
#include <cuda_fp16.h>
#include <math.h>
#include <stdint.h>

// Problem constants
#define BATCH 2
#define SEQ   2048
#define DMODEL 2048
#define FF    5632
#define NH    16
#define NKVH  4
#define HD    128
#define KD    (NKVH*HD)      // 512
#define MROWS (BATCH*SEQ)    // 4096
#define NQKV  (DMODEL + 2*KD)  // 3072

// ---------------- scratch (device globals) ----------------
__device__ __half hw_qkv[NQKV*DMODEL];    // packed q(2048)|k(512)|v(512) rows
__device__ float  g_qkvb[NQKV];           // packed biases
__device__ __half hw_o [DMODEL*DMODEL];
__device__ __half hw_g [FF*DMODEL];
__device__ __half hw_u [FF*DMODEL];
__device__ __half hw_d [DMODEL*FF];
__device__ __half g_h   [MROWS*DMODEL];
__device__ __half g_q   [MROWS*DMODEL];
__device__ __half g_k   [MROWS*KD];
__device__ __half g_vt  [KD*MROWS];       // V transposed [kv_dim][row]
__device__ __half g_attn[MROWS*DMODEL];
__device__ float  g_x1  [MROWS*DMODEL];
__device__ __half g_h2  [MROWS*DMODEL];
__device__ __half g_gate[MROWS*FF];
__device__ __half g_act [MROWS*FF];

// ---------------- helpers ----------------
__device__ __forceinline__ void cp16(uint32_t s, const void* g) {
    asm volatile("cp.async.cg.shared.global [%0], [%1], 16;\n" :: "r"(s), "l"(g));
}
__device__ __forceinline__ void cp_commit() {
    asm volatile("cp.async.commit_group;\n" ::: "memory");
}
__device__ __forceinline__ void cp_wait2() {
    asm volatile("cp.async.wait_group 2;\n" ::: "memory");
}
__device__ __forceinline__ void mma_f16(float* c,
    uint32_t a0, uint32_t a1, uint32_t a2, uint32_t a3, uint32_t b0, uint32_t b1)
{
    asm volatile("mma.sync.aligned.m16n8k16.row.col.f32.f16.f16.f32 "
        "{%0,%1,%2,%3}, {%4,%5,%6,%7}, {%8,%9}, {%0,%1,%2,%3};"
        : "+f"(c[0]), "+f"(c[1]), "+f"(c[2]), "+f"(c[3])
        : "r"(a0), "r"(a1), "r"(a2), "r"(a3), "r"(b0), "r"(b1));
}
__device__ __forceinline__ void ldsm4(uint32_t& r0, uint32_t& r1, uint32_t& r2, uint32_t& r3,
                                      uint32_t addr)
{
    asm volatile("ldmatrix.sync.aligned.m8n8.x4.shared.b16 {%0,%1,%2,%3}, [%4];"
        : "=r"(r0), "=r"(r1), "=r"(r2), "=r"(r3) : "r"(addr));
}

// ---------------- fp32 -> fp16 convert ----------------
__global__ void __launch_bounds__(256) f2h_kernel(const float* __restrict__ in,
                                                 __half* __restrict__ out, int n4)
{
    int i = blockIdx.x * 256 + threadIdx.x;
    if (i < n4) {
        float4 v = *(const float4*)(in + (size_t)i * 4);
        __half2 h0 = __floats2half2_rn(v.x, v.y);
        __half2 h1 = __floats2half2_rn(v.z, v.w);
        __half2* o = (__half2*)(out + (size_t)i * 4);
        o[0] = h0; o[1] = h1;
    }
}

__global__ void __launch_bounds__(256) pack_qkv_bias(
    const float* __restrict__ qb, const float* __restrict__ kb,
    const float* __restrict__ vb, float* __restrict__ out)
{
    int i = blockIdx.x * 256 + threadIdx.x;
    if (i < NQKV) {
        float v;
        if (i < DMODEL) v = qb[i];
        else if (i < DMODEL + KD) v = kb[i - DMODEL];
        else v = vb[i - DMODEL - KD];
        out[i] = v;
    }
}

// ---------------- RMSNorm: fp32 in, fp16 out ----------------
__global__ void __launch_bounds__(256) rmsnorm_h_kernel(
    const float* __restrict__ x, const float* __restrict__ w, __half* __restrict__ out)
{
    int row = blockIdx.x;
    int tid = threadIdx.x;
    const float4* xr = (const float4*)(x + (size_t)row * DMODEL);
    const float4* wr = (const float4*)w;
    float4 v0 = xr[tid];
    float4 v1 = xr[tid + 256];
    float ss = v0.x*v0.x + v0.y*v0.y + v0.z*v0.z + v0.w*v0.w
             + v1.x*v1.x + v1.y*v1.y + v1.z*v1.z + v1.w*v1.w;
    #pragma unroll
    for (int o = 16; o > 0; o >>= 1) ss += __shfl_xor_sync(0xffffffffu, ss, o);
    __shared__ float red[8];
    if ((tid & 31) == 0) red[tid >> 5] = ss;
    __syncthreads();
    float tot = red[0]+red[1]+red[2]+red[3]+red[4]+red[5]+red[6]+red[7];
    float inv = rsqrtf(tot / (float)DMODEL + 1e-6f);
    float4 w0 = wr[tid], w1 = wr[tid + 256];
    __half2* orow = (__half2*)(out + (size_t)row * DMODEL);
    orow[tid*2 + 0]   = __floats2half2_rn(v0.x*inv*w0.x, v0.y*inv*w0.y);
    orow[tid*2 + 1]   = __floats2half2_rn(v0.z*inv*w0.z, v0.w*inv*w0.w);
    orow[(tid+256)*2]   = __floats2half2_rn(v1.x*inv*w1.x, v1.y*inv*w1.y);
    orow[(tid+256)*2+1] = __floats2half2_rn(v1.z*inv*w1.z, v1.w*inv*w1.w);
}

// ---------------- fp16 GEMM (NT): C[M,N] = A[M,K] @ W[N,K]^T ------------------
// 128x256x64 block tile, 8 warps (2m x 4n), warp tile 64x64, m16n8k16.
// 4-stage cp.async pipeline; XOR-swizzled layout; ldmatrix.x4 fragment loads.
#define BM 128
#define BN 256
#define BKH 64
#define STG_A (BM*128)              // 16384 B
#define STG   ((BM+BN)*128)         // 49152 B
#define NSTAGE 4
#define HGEMM_SMEM (NSTAGE*STG)     // 196608 B

// flags
#define F_OUTHALF 1
#define F_TRANSC  2
#define F_QKV     4

__global__ void __launch_bounds__(256, 1) hgemm_nt(
    const __half* __restrict__ A, const __half* __restrict__ W,
    const float* __restrict__ bias, const float* __restrict__ res,
    const __half* __restrict__ gatep, void* __restrict__ Cout,
    int M, int N, int K, int flags)
{
    extern __shared__ char smem[];
    uint32_t sbase = (uint32_t)__cvta_generic_to_shared(smem);

    int tid = threadIdx.x;
    int m0 = blockIdx.y * BM, n0 = blockIdx.x * BN;
    int lane = tid & 31, wid = tid >> 5;
    int warp_m = wid >> 2;     // 0..1
    int warp_n = wid & 3;      // 0..3
    int g = lane >> 2, t4 = lane & 3;
    int lm = lane >> 3, lr = lane & 7;

    float acc[4][8][4];
    #pragma unroll
    for (int mt = 0; mt < 4; mt++)
        #pragma unroll
        for (int nt = 0; nt < 8; nt++)
            #pragma unroll
            for (int e = 0; e < 4; e++) acc[mt][nt][e] = 0.f;

    int aHi = lm >> 1;
    uint32_t aRow128[4]; int aR7[4];
    #pragma unroll
    for (int mt = 0; mt < 4; mt++) {
        int r = warp_m * 64 + mt * 16 + (lm & 1) * 8 + lr;
        aRow128[mt] = (uint32_t)r * 128; aR7[mt] = r & 7;
    }
    int bLo = lm & 1;
    uint32_t bRow128[4]; int bR7[4];
    #pragma unroll
    for (int p = 0; p < 4; p++) {
        int r = warp_n * 64 + p * 16 + (lm >> 1) * 8 + lr;
        bRow128[p] = (uint32_t)r * 128; bR7[p] = r & 7;
    }

    const __half* Abase = A + (size_t)m0 * K;
    const __half* Wbase = W + (size_t)n0 * K;

    auto issue = [&](int stage, int k0) {
        uint32_t sa = sbase + stage * STG;
        #pragma unroll
        for (int j = 0; j < 4; j++) {
            int u = tid + j * 256;
            int r = u >> 3, c = u & 7;
            cp16(sa + r*128 + ((c ^ (r & 7)) << 4),
                 Abase + (size_t)r * K + k0 + c * 8);
        }
        uint32_t sb = sa + STG_A;
        #pragma unroll
        for (int j = 0; j < 8; j++) {
            int u = tid + j * 256;
            int r = u >> 3, c = u & 7;
            cp16(sb + r*128 + ((c ^ (r & 7)) << 4),
                 Wbase + (size_t)r * K + k0 + c * 8);
        }
    };

    int nIter = K / BKH;
    issue(0, 0); cp_commit();
    issue(1, BKH); cp_commit();
    issue(2, 2*BKH); cp_commit();

    for (int it = 0; it < nIter; ++it) {
        cp_wait2();
        __syncthreads();
        if (it + 3 < nIter) issue((it + 3) % NSTAGE, (it + 3) * BKH);
        cp_commit();

        uint32_t saU = sbase + (it % NSTAGE) * STG;
        uint32_t sbU = saU + STG_A;
        #pragma unroll
        for (int kk = 0; kk < 4; kk++) {
            uint32_t a[4][4], b[8][2];
            #pragma unroll
            for (int mt = 0; mt < 4; mt++) {
                uint32_t addr = saU + aRow128[mt] + ((uint32_t)((2*kk + aHi) ^ aR7[mt]) << 4);
                ldsm4(a[mt][0], a[mt][1], a[mt][2], a[mt][3], addr);
            }
            #pragma unroll
            for (int p = 0; p < 4; p++) {
                uint32_t addr = sbU + bRow128[p] + ((uint32_t)((2*kk + bLo) ^ bR7[p]) << 4);
                ldsm4(b[2*p][0], b[2*p][1], b[2*p+1][0], b[2*p+1][1], addr);
            }
            #pragma unroll
            for (int mt = 0; mt < 4; mt++)
                #pragma unroll
                for (int nt = 0; nt < 8; nt++)
                    mma_f16(acc[mt][nt], a[mt][0], a[mt][1], a[mt][2], a[mt][3],
                            b[nt][0], b[nt][1]);
        }
        __syncthreads();
    }

    // epilogue
    bool outHalf = flags & F_OUTHALF;
    bool transC  = flags & F_TRANSC;
    bool qkv     = flags & F_QKV;
    #pragma unroll
    for (int mt = 0; mt < 4; mt++) {
        int r0 = m0 + warp_m * 64 + mt * 16 + g;
        #pragma unroll
        for (int nt = 0; nt < 8; nt++) {
            int cl = n0 + warp_n * 64 + nt * 8 + t4 * 2;
            #pragma unroll
            for (int half = 0; half < 2; half++) {
                int r = r0 + half * 8;
                float v0 = acc[mt][nt][half*2 + 0];
                float v1 = acc[mt][nt][half*2 + 1];
                if (bias) { v0 += bias[cl]; v1 += bias[cl + 1]; }
                if (qkv) {
                    if (cl < DMODEL) {
                        *(__half2*)(g_q + (size_t)r * DMODEL + cl) = __floats2half2_rn(v0, v1);
                    } else if (cl < DMODEL + KD) {
                        *(__half2*)(g_k + (size_t)r * KD + (cl - DMODEL)) = __floats2half2_rn(v0, v1);
                    } else {
                        int d = cl - DMODEL - KD;
                        g_vt[(size_t)d * MROWS + r]       = __float2half_rn(v0);
                        g_vt[(size_t)(d + 1) * MROWS + r] = __float2half_rn(v1);
                    }
                } else if (transC) {
                    __half* Ch = (__half*)Cout;
                    Ch[(size_t)cl * M + r]       = __float2half_rn(v0);
                    Ch[(size_t)(cl + 1) * M + r] = __float2half_rn(v1);
                } else {
                    size_t idx = (size_t)r * N + cl;
                    if (gatep) {
                        __half2 gh = *(const __half2*)(gatep + idx);
                        float g0 = __half2float(__low2half(gh));
                        float g1 = __half2float(__high2half(gh));
                        v0 *= g0 / (1.f + __expf(-g0));
                        v1 *= g1 / (1.f + __expf(-g1));
                    }
                    if (res) { v0 += res[idx]; v1 += res[idx + 1]; }
                    if (outHalf) {
                        *(__half2*)((__half*)Cout + idx) = __floats2half2_rn(v0, v1);
                    } else {
                        float2 p; p.x = v0; p.y = v1;
                        *(float2*)((float*)Cout + idx) = p;
                    }
                }
            }
        }
    }
}

// ---------------- Flash attention (causal, GQA rep=4), fp16 MMA ----------------
// 128 q-rows/block, 64-k tiles, 8 warps x 16 rows, online softmax.
#define AQ_OFF 0                        // Qs: 128 x 256B = 32768
#define AK_OFF 32768                    // Ks: 64 x 256B  = 16384
#define AV_OFF 49152                    // Vs: 128 x 128B = 16384
#define AS_OFF 65536                    // Ss: 128 x 65 f32 = 33280
#define AP_OFF 98816                    // Ps: 128 x 128B = 16384
#define AM_OFF 115200                   // ms/ls/cs: 3 x 128 f32 = 1536
#define ATT_SMEM (AM_OFF + 1536)

__global__ void __launch_bounds__(256) flash_attn_h(
    const __half* __restrict__ Q, const __half* __restrict__ Kb,
    const __half* __restrict__ Vt, __half* __restrict__ O)
{
    extern __shared__ char smem[];
    float* Ss  = (float*)(smem + AS_OFF);
    float* ms  = (float*)(smem + AM_OFF);
    float* ls  = ms + 128;
    float* cfs = ls + 128;

    int qt = blockIdx.x, bh = blockIdx.y;
    int b = bh >> 4, h = bh & 15, kvh = h & 3;
    int q0 = qt * 128;
    int tid = threadIdx.x;
    int lane = tid & 31, wid = tid >> 5;
    int g = lane >> 2, t4 = lane & 3;
    int wm = wid;            // 0..7 : 16 rows each
    const float scale = 0.08838834764831845f;

    // load Q tile: 128 rows x 16 chunks
    for (int u = tid; u < 128 * 16; u += 256) {
        int r = u >> 4, c = u & 15;
        uint4 v = *(const uint4*)(Q + (size_t)(b*SEQ + q0 + r) * DMODEL + h*HD + c*8);
        *(uint4*)(smem + AQ_OFF + r*256 + ((c ^ (r & 7)) << 4)) = v;
    }
    if (tid < 128) { ms[tid] = -INFINITY; ls[tid] = 0.f; }

    float co[16][4];
    #pragma unroll
    for (int nt = 0; nt < 16; nt++)
        #pragma unroll
        for (int e = 0; e < 4; e++) co[nt][e] = 0.f;

    int ktMax = 2 * qt + 1;
    for (int kt = 0; kt <= ktMax; kt++) {
        int k0 = kt * 64;
        __syncthreads();
        for (int u = tid; u < 64 * 16; u += 256) {      // K: 64 rows x 16 chunks
            int r = u >> 4, c = u & 15;
            uint4 v = *(const uint4*)(Kb + (size_t)(b*SEQ + k0 + r) * KD + kvh*HD + c*8);
            *(uint4*)(smem + AK_OFF + r*256 + ((c ^ (r & 7)) << 4)) = v;
        }
        for (int u = tid; u < 128 * 8; u += 256) {      // V^T: 128 rows x 8 chunks
            int d = u >> 3, c = u & 7;
            uint4 v = *(const uint4*)(Vt + (size_t)(kvh*HD + d) * MROWS + b*SEQ + k0 + c*8);
            *(uint4*)(smem + AV_OFF + d*128 + ((c ^ (d & 7)) << 4)) = v;
        }
        __syncthreads();

        // S = Q K^T : warp computes 16 rows x 64 cols
        float sc[8][4];
        #pragma unroll
        for (int nt = 0; nt < 8; nt++)
            #pragma unroll
            for (int e = 0; e < 4; e++) sc[nt][e] = 0.f;
        #pragma unroll
        for (int kk = 0; kk < 8; kk++) {
            int r0 = wm * 16 + g, r1 = r0 + 8;
            uint32_t a0 = *(const uint32_t*)(smem + AQ_OFF + r0*256 + (((2*kk  ) ^ (r0 & 7)) << 4) + t4*4);
            uint32_t a1 = *(const uint32_t*)(smem + AQ_OFF + r1*256 + (((2*kk  ) ^ (r1 & 7)) << 4) + t4*4);
            uint32_t a2 = *(const uint32_t*)(smem + AQ_OFF + r0*256 + (((2*kk+1) ^ (r0 & 7)) << 4) + t4*4);
            uint32_t a3 = *(const uint32_t*)(smem + AQ_OFF + r1*256 + (((2*kk+1) ^ (r1 & 7)) << 4) + t4*4);
            #pragma unroll
            for (int nt = 0; nt < 8; nt++) {
                int rb = nt * 8 + g;
                uint32_t b0 = *(const uint32_t*)(smem + AK_OFF + rb*256 + (((2*kk  ) ^ (rb & 7)) << 4) + t4*4);
                uint32_t b1 = *(const uint32_t*)(smem + AK_OFF + rb*256 + (((2*kk+1) ^ (rb & 7)) << 4) + t4*4);
                mma_f16(sc[nt], a0, a1, a2, a3, b0, b1);
            }
        }
        {
            int rr = wm * 16 + g;
            #pragma unroll
            for (int nt = 0; nt < 8; nt++) {
                int cc = nt * 8 + t4 * 2;
                Ss[rr*65 + cc]       = sc[nt][0] * scale;
                Ss[rr*65 + cc + 1]   = sc[nt][1] * scale;
                Ss[(rr+8)*65 + cc]   = sc[nt][2] * scale;
                Ss[(rr+8)*65 + cc+1] = sc[nt][3] * scale;
            }
        }
        __syncthreads();

        // online softmax: 2 threads per row (256 threads, 128 rows)
        {
            int r = tid >> 1, hf = tid & 1;
            int cm = q0 + r - k0 + 1;
            int cmax = cm < 0 ? 0 : (cm > 64 ? 64 : cm);
            int lo = hf * 32;
            int hi = cmax < lo + 32 ? cmax : lo + 32;
            float mx = -INFINITY;
            for (int c = lo; c < hi; c++) mx = fmaxf(mx, Ss[r*65 + c]);
            mx = fmaxf(mx, __shfl_xor_sync(0xffffffffu, mx, 1));
            float mprev = ms[r];
            float mxn = fmaxf(mx, mprev);
            float sum = 0.f;
            for (int c = lo; c < lo + 32; c += 2) {
                float p0 = (c     < cmax) ? __expf(Ss[r*65 + c]     - mxn) : 0.f;
                float p1 = (c + 1 < cmax) ? __expf(Ss[r*65 + c + 1] - mxn) : 0.f;
                sum += p0 + p1;
                int u = c >> 1;
                *(__half2*)(smem + AP_OFF + r*128 + (((u >> 2) ^ (r & 7)) << 4) + (u & 3)*4)
                    = __floats2half2_rn(p0, p1);
            }
            sum += __shfl_xor_sync(0xffffffffu, sum, 1);
            if (hf == 0) {
                float corr = __expf(mprev - mxn);
                ls[r] = ls[r] * corr + sum;
                ms[r] = mxn;
                cfs[r] = corr;
            }
        }
        __syncthreads();

        // rescale, then O += P V : warp 16 rows x 128 cols
        float c0 = cfs[wm*16 + g], c1 = cfs[wm*16 + 8 + g];
        #pragma unroll
        for (int nt = 0; nt < 16; nt++) {
            co[nt][0] *= c0; co[nt][1] *= c0;
            co[nt][2] *= c1; co[nt][3] *= c1;
        }
        #pragma unroll
        for (int kk = 0; kk < 4; kk++) {
            int r0 = wm * 16 + g, r1 = r0 + 8;
            uint32_t a0 = *(const uint32_t*)(smem + AP_OFF + r0*128 + (((2*kk  ) ^ (r0 & 7)) << 4) + t4*4);
            uint32_t a1 = *(const uint32_t*)(smem + AP_OFF + r1*128 + (((2*kk  ) ^ (r1 & 7)) << 4) + t4*4);
            uint32_t a2 = *(const uint32_t*)(smem + AP_OFF + r0*128 + (((2*kk+1) ^ (r0 & 7)) << 4) + t4*4);
            uint32_t a3 = *(const uint32_t*)(smem + AP_OFF + r1*128 + (((2*kk+1) ^ (r1 & 7)) << 4) + t4*4);
            #pragma unroll
            for (int nt = 0; nt < 16; nt++) {
                int d = nt * 8 + g;
                uint32_t b0 = *(const uint32_t*)(smem + AV_OFF + d*128 + (((2*kk  ) ^ (d & 7)) << 4) + t4*4);
                uint32_t b1 = *(const uint32_t*)(smem + AV_OFF + d*128 + (((2*kk+1) ^ (d & 7)) << 4) + t4*4);
                mma_f16(co[nt], a0, a1, a2, a3, b0, b1);
            }
        }
    }

    int r0 = wm * 16 + g;
    float inv0 = 1.f / ls[r0];
    float inv1 = 1.f / ls[r0 + 8];
    #pragma unroll
    for (int nt = 0; nt < 16; nt++) {
        int cc = h*HD + nt * 8 + t4 * 2;
        *(__half2*)(O + (size_t)(b*SEQ + q0 + r0) * DMODEL + cc)
            = __floats2half2_rn(co[nt][0]*inv0, co[nt][1]*inv0);
        *(__half2*)(O + (size_t)(b*SEQ + q0 + r0 + 8) * DMODEL + cc)
            = __floats2half2_rn(co[nt][2]*inv1, co[nt][3]*inv1);
    }
}

// ---------------- host launcher ----------------
extern "C" void kernel_launch(void* const* d_in, const int* in_sizes, int n_in,
                              void* d_out, int out_size)
{
    const float* x      = (const float*)d_in[0];
    const float* ln1_w  = (const float*)d_in[1];
    const float* q_w    = (const float*)d_in[2];
    const float* q_b    = (const float*)d_in[3];
    const float* k_w    = (const float*)d_in[4];
    const float* k_b    = (const float*)d_in[5];
    const float* v_w    = (const float*)d_in[6];
    const float* v_b    = (const float*)d_in[7];
    const float* o_w    = (const float*)d_in[8];
    const float* ln2_w  = (const float*)d_in[9];
    const float* gate_w = (const float*)d_in[10];
    const float* up_w   = (const float*)d_in[11];
    const float* down_w = (const float*)d_in[12];
    float* out = (float*)d_out;

    __half *wqkv, *wo, *wg, *wu, *wd;
    __half *h, *q, *k, *vt, *attn, *h2, *act, *gate;
    float *x1, *qkvb;
    cudaGetSymbolAddress((void**)&wqkv, hw_qkv);
    cudaGetSymbolAddress((void**)&qkvb, g_qkvb);
    cudaGetSymbolAddress((void**)&wo, hw_o);
    cudaGetSymbolAddress((void**)&wg, hw_g);
    cudaGetSymbolAddress((void**)&wu, hw_u);
    cudaGetSymbolAddress((void**)&wd, hw_d);
    cudaGetSymbolAddress((void**)&h,    g_h);
    cudaGetSymbolAddress((void**)&q,    g_q);
    cudaGetSymbolAddress((void**)&k,    g_k);
    cudaGetSymbolAddress((void**)&vt,   g_vt);
    cudaGetSymbolAddress((void**)&attn, g_attn);
    cudaGetSymbolAddress((void**)&x1,   g_x1);
    cudaGetSymbolAddress((void**)&h2,   g_h2);
    cudaGetSymbolAddress((void**)&gate, g_gate);
    cudaGetSymbolAddress((void**)&act,  g_act);

    cudaFuncSetAttribute(hgemm_nt,
                         cudaFuncAttributeMaxDynamicSharedMemorySize, HGEMM_SMEM);
    cudaFuncSetAttribute(flash_attn_h,
                         cudaFuncAttributeMaxDynamicSharedMemorySize, ATT_SMEM);

    // 0) weights -> fp16 (q/k/v packed into one buffer)
    auto cvt = [&](const float* src, __half* dst, int n) {
        int n4 = n / 4;
        f2h_kernel<<<(n4 + 255) / 256, 256>>>(src, dst, n4);
    };
    cvt(q_w,    wqkv,                               DMODEL*DMODEL);
    cvt(k_w,    wqkv + (size_t)DMODEL*DMODEL,       KD*DMODEL);
    cvt(v_w,    wqkv + (size_t)(DMODEL+KD)*DMODEL,  KD*DMODEL);
    cvt(o_w,    wo, DMODEL*DMODEL);
    cvt(gate_w, wg, FF*DMODEL);
    cvt(up_w,   wu, FF*DMODEL);
    cvt(down_w, wd, DMODEL*FF);
    pack_qkv_bias<<<(NQKV + 255) / 256, 256>>>(q_b, k_b, v_b, qkvb);

    // 1) h = rmsnorm(x) -> fp16
    rmsnorm_h_kernel<<<MROWS, 256>>>(x, ln1_w, h);

    // 2) fused q/k/v projection
    hgemm_nt<<<dim3(NQKV/BN, MROWS/BM), 256, HGEMM_SMEM>>>(
        h, wqkv, qkvb, nullptr, nullptr, nullptr, MROWS, NQKV, DMODEL, F_QKV);

    // 3) attention (128-row q tiles)
    flash_attn_h<<<dim3(SEQ/128, BATCH*NH), 256, ATT_SMEM>>>(q, k, vt, attn);

    // 4) x1 = x + attn @ o_w^T  (fp32 out)
    hgemm_nt<<<dim3(DMODEL/BN, MROWS/BM), 256, HGEMM_SMEM>>>(
        attn, wo, nullptr, x, nullptr, x1, MROWS, DMODEL, DMODEL, 0);

    // 5) h2 = rmsnorm(x1) -> fp16
    rmsnorm_h_kernel<<<MROWS, 256>>>(x1, ln2_w, h2);

    // 6) SwiGLU
    hgemm_nt<<<dim3(FF/BN, MROWS/BM), 256, HGEMM_SMEM>>>(
        h2, wg, nullptr, nullptr, nullptr, gate, MROWS, FF, DMODEL, F_OUTHALF);
    hgemm_nt<<<dim3(FF/BN, MROWS/BM), 256, HGEMM_SMEM>>>(
        h2, wu, nullptr, nullptr, gate, act, MROWS, FF, DMODEL, F_OUTHALF);

    // 7) out = x1 + act @ down_w^T  (fp32 out)
    hgemm_nt<<<dim3(DMODEL/BN, MROWS/BM), 256, HGEMM_SMEM>>>(
        act, wd, nullptr, x1, nullptr, out, MROWS, DMODEL, FF, 0);
}